// round 1
// baseline (speedup 1.0000x reference)
#include <cuda_runtime.h>
#include <math.h>

#define BS 8
#define LL 4800
#define D 256
#define H 8
#define DH 32
#define ROWS (BS*LL)   // 38400
#define TOK 8

// ---------------- scratch (device globals; no runtime allocation) ----------------
__device__ float g_q   [BS*LL*D];
__device__ float g_k   [BS*LL*D];
__device__ float g_v   [BS*LL*D];
__device__ float g_qp  [BS*LL*D];
__device__ float g_kp  [BS*LL*D];
__device__ float g_vp  [BS*LL*D];
__device__ float g_msg [BS*LL*D];
__device__ float g_tmp [BS*LL*D];
__device__ float g_xmid[BS*LL*D];
__device__ float g_hcat[BS*LL*2*D];
__device__ float g_t1  [BS*LL*2*D];
__device__ float g_kv  [BS*H*DH*DH];
__device__ float g_ksum[BS*H*DH];

__device__ __forceinline__ float phi(float x) {       // elu(x)+1
    return x > 0.f ? x + 1.f : __expf(x);
}
__device__ __forceinline__ float warp_sum(float v) {
    #pragma unroll
    for (int o = 16; o; o >>= 1) v += __shfl_xor_sync(0xffffffffu, v, o);
    return v;
}

// ---------------- SGEMM: C[M,N] = A[M,K] @ B[K,N], row-major, EPI=1 -> relu ----------------
template<int EPI>
__global__ void __launch_bounds__(256) sgemm(const float* __restrict__ A,
                                             const float* __restrict__ B,
                                             float* __restrict__ C,
                                             int M, int N, int K) {
    __shared__ float As[16][64];
    __shared__ float Bs[16][64];
    const int t  = threadIdx.x;
    const int bm = blockIdx.y * 64, bn = blockIdx.x * 64;
    const int tx = t & 15, ty = t >> 4;
    const int ar = t >> 2, ac = (t & 3) << 2;   // A tile: 64 rows x 16 k
    const int br = t >> 4, bc = (t & 15) << 2;  // B tile: 16 k x 64 cols
    float acc[4][4] = {};
    for (int k0 = 0; k0 < K; k0 += 16) {
        float4 a4 = *(const float4*)(A + (size_t)(bm + ar) * K + k0 + ac);
        As[ac + 0][ar] = a4.x; As[ac + 1][ar] = a4.y;
        As[ac + 2][ar] = a4.z; As[ac + 3][ar] = a4.w;
        *(float4*)(&Bs[br][bc]) = *(const float4*)(B + (size_t)(k0 + br) * N + bn + bc);
        __syncthreads();
        #pragma unroll
        for (int k = 0; k < 16; k++) {
            float4 av = *(const float4*)(&As[k][ty * 4]);
            float4 bv = *(const float4*)(&Bs[k][tx * 4]);
            float a[4] = {av.x, av.y, av.z, av.w};
            float b[4] = {bv.x, bv.y, bv.z, bv.w};
            #pragma unroll
            for (int i = 0; i < 4; i++)
                #pragma unroll
                for (int j = 0; j < 4; j++)
                    acc[i][j] += a[i] * b[j];
        }
        __syncthreads();
    }
    #pragma unroll
    for (int i = 0; i < 4; i++) {
        float4 o;
        o.x = acc[i][0]; o.y = acc[i][1]; o.z = acc[i][2]; o.w = acc[i][3];
        if (EPI == 1) {
            o.x = fmaxf(o.x, 0.f); o.y = fmaxf(o.y, 0.f);
            o.z = fmaxf(o.z, 0.f); o.w = fmaxf(o.w, 0.f);
        }
        *(float4*)(C + (size_t)(bm + ty * 4 + i) * N + bn + tx * 4) = o;
    }
}

// ---------------- permutation gathers (p13 / p21 / p32 views) ----------------
__global__ void __launch_bounds__(256) permute_k(const float* __restrict__ src,
                                                 float* __restrict__ dst, int mode) {
    int i = blockIdx.x * 256 + threadIdx.x;
    if (i >= BS * LL * D) return;
    int b = i / (LL * D);
    int F = i % (LL * D);
    int l0, c0;
    if (mode == 13) {                  // per-token [h,dh] transpose reinterpreted
        int f = F % D; l0 = F / D;
        c0 = (f & 7) * 32 + (f >> 3);
    } else if (mode == 21) {           // [h,L,dh] flattened
        int h0  = F / (LL * DH);
        int rem = F % (LL * DH);
        l0 = rem / DH;
        c0 = h0 * 32 + (rem % DH);
    } else {                           // mode 32: [dh,h,L] flattened
        int d0  = F / (H * LL);
        int rem = F % (H * LL);
        int h0  = rem / LL;
        l0 = rem % LL;
        c0 = h0 * 32 + d0;
    }
    dst[i] = src[(size_t)b * LL * D + (size_t)l0 * D + c0];
}

// ---------------- KV = sum_s phi(K)[s,d] * V[s,e];  Ksum = sum_s phi(K) ----------------
__global__ void __launch_bounds__(256) kv_reduce(const float* __restrict__ k,
                                                 const float* __restrict__ v) {
    int b = blockIdx.x >> 3, h = blockIdx.x & 7;
    const float* kb = k + (size_t)b * LL * D + h * DH;
    const float* vb = v + (size_t)b * LL * D + h * DH;
    __shared__ float ks[8][32], vs[8][32];
    int t = threadIdx.x;
    int r = t >> 5, c = t & 31;
    float acc[4] = {0.f, 0.f, 0.f, 0.f};
    float ksacc = 0.f;
    for (int s0 = 0; s0 < LL; s0 += 8) {
        ks[r][c] = phi(kb[(size_t)(s0 + r) * D + c]);
        vs[r][c] = vb[(size_t)(s0 + r) * D + c];
        __syncthreads();
        #pragma unroll
        for (int row = 0; row < 8; row++) {
            float ve = vs[row][c];
            #pragma unroll
            for (int jj = 0; jj < 4; jj++)
                acc[jj] += ks[row][r + jj * 8] * ve;
        }
        if (t < 32) {
            #pragma unroll
            for (int row = 0; row < 8; row++) ksacc += ks[row][t];
        }
        __syncthreads();
    }
    float* kvout = g_kv + (size_t)(b * H + h) * DH * DH;
    #pragma unroll
    for (int jj = 0; jj < 4; jj++)
        kvout[(r + jj * 8) * DH + c] = acc[jj];
    if (t < 32) g_ksum[(b * H + h) * DH + t] = ksacc;
}

// ---------------- msg[l,c] = (phi(Q)[l,h,:] . KV[h,:,e]) / (phi(Q)[l,h,:].Ksum[h,:] + eps) ----------------
__global__ void __launch_bounds__(256) attn_out(const float* __restrict__ q,
                                                float* __restrict__ msg) {
    int b  = blockIdx.y;
    int l0 = blockIdx.x * TOK;
    __shared__ float sKV[H * DH * DH];   // [h][d][e]
    __shared__ float sKs[H * DH];
    __shared__ float sQ[TOK][D];
    __shared__ float sZ[TOK][H];
    int t = threadIdx.x;
    const float* kvb = g_kv + (size_t)b * H * DH * DH;
    #pragma unroll
    for (int i = t; i < H * DH * DH; i += 256) sKV[i] = kvb[i];
    if (t < H * DH) sKs[t] = g_ksum[b * H * DH + t];
    const float* qb = q + (size_t)b * LL * D + (size_t)l0 * D;
    #pragma unroll
    for (int jj = 0; jj < TOK; jj++) sQ[jj][t] = phi(qb[jj * D + t]);
    __syncthreads();
    if (t < TOK * H) {
        int tok = t / H, h = t % H;
        float z = 0.f;
        #pragma unroll
        for (int d = 0; d < DH; d++) z += sQ[tok][h * DH + d] * sKs[h * DH + d];
        sZ[tok][h] = 1.f / (z + 1e-6f);
    }
    __syncthreads();
    int c = t, h = c >> 5, e = c & 31;
    float* mout = msg + (size_t)b * LL * D + (size_t)l0 * D;
    #pragma unroll
    for (int jj = 0; jj < TOK; jj++) {
        float dot = 0.f;
        #pragma unroll
        for (int d = 0; d < DH; d++)
            dot += sQ[jj][h * DH + d] * sKV[(h * DH + d) * DH + e];
        mout[jj * D + c] = dot * sZ[jj][h];
    }
}

// ---------------- hcat = [xb | layernorm(tmp; g1,b1)] ----------------
__global__ void __launch_bounds__(256) build_hcat(const float* __restrict__ tmp,
                                                  const float* __restrict__ xb,
                                                  const float* __restrict__ g,
                                                  const float* __restrict__ bta,
                                                  float* __restrict__ hcat) {
    int warp = threadIdx.x >> 5, lane = threadIdx.x & 31;
    size_t row = (size_t)blockIdx.x * 8 + warp;
    const float* rt = tmp + row * D;
    float v[8]; float s = 0.f;
    #pragma unroll
    for (int i = 0; i < 8; i++) { v[i] = rt[lane + 32 * i]; s += v[i]; }
    s = warp_sum(s);
    float mean = s * (1.f / D);
    float s2 = 0.f;
    #pragma unroll
    for (int i = 0; i < 8; i++) { float d0 = v[i] - mean; s2 += d0 * d0; }
    s2 = warp_sum(s2);
    float rstd = rsqrtf(s2 * (1.f / D) + 1e-5f);
    const float* rx = xb + row * D;
    float* ho = hcat + row * 2 * D;
    #pragma unroll
    for (int i = 0; i < 8; i++) {
        int c = lane + 32 * i;
        ho[D + c] = (v[i] - mean) * rstd * g[c] + bta[c];
        ho[c] = rx[c];
    }
}

// ---------------- acc += 0.5 * layernorm(tmp; g2,b2) ----------------
__global__ void __launch_bounds__(256) ln_acc(const float* __restrict__ tmp,
                                              const float* __restrict__ g,
                                              const float* __restrict__ bta,
                                              float* __restrict__ acc) {
    int warp = threadIdx.x >> 5, lane = threadIdx.x & 31;
    size_t row = (size_t)blockIdx.x * 8 + warp;
    const float* rt = tmp + row * D;
    float v[8]; float s = 0.f;
    #pragma unroll
    for (int i = 0; i < 8; i++) { v[i] = rt[lane + 32 * i]; s += v[i]; }
    s = warp_sum(s);
    float mean = s * (1.f / D);
    float s2 = 0.f;
    #pragma unroll
    for (int i = 0; i < 8; i++) { float d0 = v[i] - mean; s2 += d0 * d0; }
    s2 = warp_sum(s2);
    float rstd = rsqrtf(s2 * (1.f / D) + 1e-5f);
    float* ao = acc + row * D;
    #pragma unroll
    for (int i = 0; i < 8; i++) {
        int c = lane + 32 * i;
        ao[c] += 0.5f * ((v[i] - mean) * rstd * g[c] + bta[c]);
    }
}

__global__ void __launch_bounds__(256) copy4(const float4* __restrict__ src,
                                             float4* __restrict__ dst, int n) {
    int i = blockIdx.x * 256 + threadIdx.x;
    if (i < n) dst[i] = src[i];
}

// ---------------- host orchestration ----------------
extern "C" void kernel_launch(void* const* d_in, const int* in_sizes, int n_in,
                              void* d_out, int out_size) {
    (void)in_sizes; (void)n_in; (void)out_size;
    const float* x   = (const float*)d_in[0];
    const float* src = (const float*)d_in[1];
    const float* Wq  = (const float*)d_in[2];
    const float* Wk  = (const float*)d_in[3];
    const float* Wv  = (const float*)d_in[4];
    const float* Wm  = (const float*)d_in[5];
    const float* W1  = (const float*)d_in[6];
    const float* W2  = (const float*)d_in[7];
    const float* g1  = (const float*)d_in[8];
    const float* b1  = (const float*)d_in[9];
    const float* g2  = (const float*)d_in[10];
    const float* b2  = (const float*)d_in[11];
    float* out = (float*)d_out;

    float *q, *k, *v, *qp, *kp, *vp, *msg, *tmp, *xmid, *hcat, *t1;
    cudaGetSymbolAddress((void**)&q,    g_q);
    cudaGetSymbolAddress((void**)&k,    g_k);
    cudaGetSymbolAddress((void**)&v,    g_v);
    cudaGetSymbolAddress((void**)&qp,   g_qp);
    cudaGetSymbolAddress((void**)&kp,   g_kp);
    cudaGetSymbolAddress((void**)&vp,   g_vp);
    cudaGetSymbolAddress((void**)&msg,  g_msg);
    cudaGetSymbolAddress((void**)&tmp,  g_tmp);
    cudaGetSymbolAddress((void**)&xmid, g_xmid);
    cudaGetSymbolAddress((void**)&hcat, g_hcat);
    cudaGetSymbolAddress((void**)&t1,   g_t1);

    dim3 thr(256);
    auto gemm = [&](const float* A, const float* B, float* C,
                    int M, int N, int K, int relu) {
        dim3 grid(N / 64, M / 64);
        if (relu) sgemm<1><<<grid, thr>>>(A, B, C, M, N, K);
        else      sgemm<0><<<grid, thr>>>(A, B, C, M, N, K);
    };

    // projections
    gemm(x,   Wq, q, ROWS, D, D, 0);
    gemm(src, Wk, k, ROWS, D, D, 0);
    gemm(src, Wv, v, ROWS, D, D, 0);

    // x_mid accumulator starts as x
    copy4<<<ROWS * D / 4 / 256, thr>>>((const float4*)x, (float4*)xmid, ROWS * D / 4);

    auto block = [&](const float* xb, int mode, float* accbuf) {
        const float *qq = q, *kk = k, *vv = v;
        if (mode) {
            permute_k<<<ROWS * D / 256, thr>>>(q, qp, mode);
            permute_k<<<ROWS * D / 256, thr>>>(k, kp, mode);
            permute_k<<<ROWS * D / 256, thr>>>(v, vp, mode);
            qq = qp; kk = kp; vv = vp;
        }
        kv_reduce<<<BS * H, thr>>>(kk, vv);
        attn_out<<<dim3(LL / TOK, BS), thr>>>(qq, msg);
        gemm(msg, Wm, tmp, ROWS, D, D, 0);
        build_hcat<<<ROWS / 8, thr>>>(tmp, xb, g1, b1, hcat);
        gemm(hcat, W1, t1, ROWS, 2 * D, 2 * D, 1);
        gemm(t1, W2, tmp, ROWS, D, 2 * D, 0);
        ln_acc<<<ROWS / 8, thr>>>(tmp, g2, b2, accbuf);
    };

    // x_mid = x + 0.5*(m + m3)
    block(x, 0,  xmid);
    block(x, 13, xmid);
    // out = x_mid + 0.5*(m1 + m2)
    copy4<<<ROWS * D / 4 / 256, thr>>>((const float4*)xmid, (float4*)out, ROWS * D / 4);
    block(xmid, 21, out);
    block(xmid, 32, out);
}

// round 3
// speedup vs baseline: 3.3694x; 3.3694x over previous
#include <cuda_runtime.h>
#include <cuda_bf16.h>
#include <math.h>
#include <stdint.h>

#if defined(__CUDA_ARCH__) && defined(__CUDA_ARCH_FEAT_SM103_ALL)
#define HAS_TCGEN05 1
#else
#define HAS_TCGEN05 0
#endif

#define BS 8
#define LL 4800
#define D 256
#define H 8
#define DH 32
#define ROWS (BS*LL)   // 38400
#define TOK 8

#define BM 128
#define BN 256
#define BK 64
// per-stage smem layout (bytes): Ahi 16K | Alo 16K | Bhi 32K | Blo 32K
#define A_HI 0
#define A_LO 16384
#define B_HI 32768
#define B_LO 65536
#define STAGE_BYTES 98304
#define SMEM_DYN (2*STAGE_BYTES + 1024)

// ---------------- scratch (device globals) ----------------
__device__ float g_q   [BS*LL*D];
__device__ float g_k   [BS*LL*D];
__device__ float g_v   [BS*LL*D];
__device__ float g_qp  [BS*LL*D];
__device__ float g_kp  [BS*LL*D];
__device__ float g_vp  [BS*LL*D];
__device__ float g_tmp [BS*LL*D];
__device__ float g_xmid[BS*LL*D];
__device__ float g_kv  [BS*H*DH*DH];
__device__ float g_ksum[BS*H*DH];

// bf16 hi/lo activation buffers (widest use: 512 cols)
__device__ __nv_bfloat16 g_xhi[ROWS*2*D];
__device__ __nv_bfloat16 g_xlo[ROWS*2*D];
__device__ __nv_bfloat16 g_thi[ROWS*2*D];
__device__ __nv_bfloat16 g_tlo[ROWS*2*D];

// transposed bf16 weights [N,K]
__device__ __nv_bfloat16 g_wqh[D*D],     g_wql[D*D];
__device__ __nv_bfloat16 g_wkh[D*D],     g_wkl[D*D];
__device__ __nv_bfloat16 g_wvh[D*D],     g_wvl[D*D];
__device__ __nv_bfloat16 g_wmh[D*D],     g_wml[D*D];
__device__ __nv_bfloat16 g_w1h[2*D*2*D], g_w1l[2*D*2*D];
__device__ __nv_bfloat16 g_w2h[D*2*D],   g_w2l[D*2*D];

// ---------------- small helpers ----------------
__device__ __forceinline__ float phi(float x) { return x > 0.f ? x + 1.f : __expf(x); }
__device__ __forceinline__ float warp_sum(float v) {
    #pragma unroll
    for (int o = 16; o; o >>= 1) v += __shfl_xor_sync(0xffffffffu, v, o);
    return v;
}
__device__ __forceinline__ uint32_t smem_u32(const void* p) {
    uint32_t a;
    asm("{ .reg .u64 t; cvta.to.shared.u64 t, %1; cvt.u32.u64 %0, t; }" : "=r"(a) : "l"(p));
    return a;
}
#if HAS_TCGEN05
__device__ __forceinline__ void mbar_init(uint32_t a, uint32_t cnt) {
    asm volatile("mbarrier.init.shared.b64 [%0], %1;" :: "r"(a), "r"(cnt) : "memory");
}
__device__ __forceinline__ void mbar_wait(uint32_t a, uint32_t parity) {
    asm volatile(
        "{\n\t.reg .pred P;\n"
        "W_%=:\n\t"
        "mbarrier.try_wait.parity.acquire.cta.shared::cta.b64 P, [%0], %1, 0x989680;\n\t"
        "@!P bra W_%=;\n\t}"
        :: "r"(a), "r"(parity) : "memory");
}
// SW128 base descriptor: layout=SW128, version=1(Blackwell), SBO=64, LBO=1
__device__ __forceinline__ uint64_t make_desc(uint32_t addr) {
    const uint64_t base = (uint64_t(2) << 61) | (uint64_t(1) << 46)
                        | (uint64_t(64) << 32) | (uint64_t(1) << 16);
    return base | ((uint64_t)(addr >> 4) & 0x3FFF);
}
__device__ __forceinline__ void mma_f16_ss(uint32_t d, uint64_t a, uint64_t b,
                                           uint32_t idesc, uint32_t en) {
    asm volatile(
        "{\n\t.reg .pred p;\n\tsetp.ne.u32 p, %5, 0;\n\t"
        "tcgen05.mma.cta_group::1.kind::f16 [%0], %1, %2, %3, {%4, %4, %4, %4}, p;\n\t}"
        :: "r"(d), "l"(a), "l"(b), "r"(idesc), "r"(0u), "r"(en) : "memory");
}
__device__ __forceinline__ void tc_commit(uint32_t mbar) {
    asm volatile(
        "tcgen05.commit.cta_group::1.mbarrier::arrive::one.shared::cluster.b64 [%0];"
        :: "r"(mbar) : "memory");
}
#endif

// ---------------- convert kernels ----------------
__global__ void __launch_bounds__(256) aconv(const float4* __restrict__ a,
                                             __nv_bfloat162* __restrict__ hi,
                                             __nv_bfloat162* __restrict__ lo, int n4) {
    int i = blockIdx.x * 256 + threadIdx.x;
    if (i >= n4) return;
    float4 v = a[i];
    __nv_bfloat16 h0 = __float2bfloat16(v.x), h1 = __float2bfloat16(v.y);
    __nv_bfloat16 h2 = __float2bfloat16(v.z), h3 = __float2bfloat16(v.w);
    hi[2*i]   = __halves2bfloat162(h0, h1);
    hi[2*i+1] = __halves2bfloat162(h2, h3);
    lo[2*i]   = __halves2bfloat162(__float2bfloat16(v.x - __bfloat162float(h0)),
                                   __float2bfloat16(v.y - __bfloat162float(h1)));
    lo[2*i+1] = __halves2bfloat162(__float2bfloat16(v.z - __bfloat162float(h2)),
                                   __float2bfloat16(v.w - __bfloat162float(h3)));
}

__global__ void __launch_bounds__(256) wconv(const float* __restrict__ W,
                                             __nv_bfloat16* __restrict__ hi,
                                             __nv_bfloat16* __restrict__ lo,
                                             int K, int N) {
    int i = blockIdx.x * 256 + threadIdx.x;
    if (i >= N * K) return;
    int n = i / K, k = i % K;
    float v = W[(size_t)k * N + n];
    __nv_bfloat16 h = __float2bfloat16(v);
    hi[i] = h;
    lo[i] = __float2bfloat16(v - __bfloat162float(h));
}

// ---------------- tcgen05 GEMM: C[M,N] = (Ahi+Alo)[M,K] @ (Bhi+Blo)[N,K]^T ----------------
__device__ __forceinline__ void load_stage(char* st,
        const __nv_bfloat16* __restrict__ Ahi, const __nv_bfloat16* __restrict__ Alo,
        const __nv_bfloat16* __restrict__ Bhi, const __nv_bfloat16* __restrict__ Blo,
        int bm, int bn, int k0, int K, int t) {
    #pragma unroll
    for (int it = 0; it < 4; it++) {              // A: 128 rows x 8 vec
        int i = t + it * 256;
        int row = i >> 3, j = i & 7;
        uint32_t off = row * 128 + j * 16;
        uint32_t sw = off ^ ((off >> 3) & 0x70);
        size_t g = (size_t)(bm + row) * K + k0 + j * 8;
        *(uint4*)(st + A_HI + sw) = *(const uint4*)(Ahi + g);
        *(uint4*)(st + A_LO + sw) = *(const uint4*)(Alo + g);
    }
    #pragma unroll
    for (int it = 0; it < 8; it++) {              // B: 256 rows x 8 vec
        int i = t + it * 256;
        int row = i >> 3, j = i & 7;
        uint32_t off = row * 128 + j * 16;
        uint32_t sw = off ^ ((off >> 3) & 0x70);
        size_t g = (size_t)(bn + row) * K + k0 + j * 8;
        *(uint4*)(st + B_HI + sw) = *(const uint4*)(Bhi + g);
        *(uint4*)(st + B_LO + sw) = *(const uint4*)(Blo + g);
    }
}

template<int EPI>   // 0: fp32 out; 1: relu -> bf16 hi/lo out
__global__ void __launch_bounds__(256, 1) tc_gemm(
        const __nv_bfloat16* __restrict__ Ahi, const __nv_bfloat16* __restrict__ Alo,
        const __nv_bfloat16* __restrict__ Bhi, const __nv_bfloat16* __restrict__ Blo,
        float* __restrict__ Cf,
        __nv_bfloat16* __restrict__ Chi, __nv_bfloat16* __restrict__ Clo,
        int K, int N) {
#if HAS_TCGEN05
    extern __shared__ char dsm_raw[];
    char* sbase = (char*)(((uintptr_t)dsm_raw + 1023) & ~(uintptr_t)1023);
    __shared__ uint32_t s_tmem;
    __shared__ __align__(8) unsigned long long s_mbar[2];
    const uint32_t mb = smem_u32(s_mbar);
    const int t = threadIdx.x, wid = t >> 5;

    if (wid == 0) {
        asm volatile("tcgen05.alloc.cta_group::1.sync.aligned.shared::cta.b32 [%0], %1;"
                     :: "r"(smem_u32(&s_tmem)), "r"(256u) : "memory");
        asm volatile("tcgen05.relinquish_alloc_permit.cta_group::1.sync.aligned;");
    }
    if (t == 0) { mbar_init(mb, 1); mbar_init(mb + 8, 1); }
    __syncthreads();
    const uint32_t tmem = s_tmem;

    const int bm = blockIdx.y * BM, bn = blockIdx.x * BN;
    const int NC = K >> 6;
    const uint32_t idesc = (1u << 4) | (1u << 7) | (1u << 10)
                         | ((BN / 8) << 17) | ((BM / 16) << 24);

    load_stage(sbase, Ahi, Alo, Bhi, Blo, bm, bn, 0, K, t);
    asm volatile("fence.proxy.async.shared::cta;" ::: "memory");
    __syncthreads();

    int ph0 = 0, ph1 = 0;
    const uint32_t sb32 = smem_u32(sbase);
    for (int c = 0; c < NC; c++) {
        const int s = c & 1;
        if (t == 0) {
            uint32_t st = sb32 + s * STAGE_BYTES;
            uint64_t dAh = make_desc(st + A_HI), dAl = make_desc(st + A_LO);
            uint64_t dBh = make_desc(st + B_HI), dBl = make_desc(st + B_LO);
            #pragma unroll
            for (int k = 0; k < 4; k++) {
                mma_f16_ss(tmem, dAh + k * 2, dBh + k * 2, idesc, !(c == 0 && k == 0));
                mma_f16_ss(tmem, dAh + k * 2, dBl + k * 2, idesc, 1u);
                mma_f16_ss(tmem, dAl + k * 2, dBh + k * 2, idesc, 1u);
            }
            tc_commit(mb + s * 8);
        }
        if (c + 1 < NC) {
            if (c >= 1) {   // stage s^1 was used by MMA(c-1): wait before overwrite
                if ((s ^ 1) == 0) { mbar_wait(mb,     ph0); ph0 ^= 1; }
                else              { mbar_wait(mb + 8, ph1); ph1 ^= 1; }
            }
            load_stage(sbase + ((c + 1) & 1) * STAGE_BYTES,
                       Ahi, Alo, Bhi, Blo, bm, bn, (c + 1) * BK, K, t);
            asm volatile("fence.proxy.async.shared::cta;" ::: "memory");
            __syncthreads();
        }
    }
    const int sl = (NC - 1) & 1;
    if (sl == 0) mbar_wait(mb, ph0); else mbar_wait(mb + 8, ph1);
    asm volatile("tcgen05.fence::after_thread_sync;" ::: "memory");

    if (wid < 4) {
        const int row = bm + wid * 32 + (t & 31);
        #pragma unroll
        for (int ch = 0; ch < 8; ch++) {
            uint32_t r[32];
            asm volatile(
                "tcgen05.ld.sync.aligned.32x32b.x32.b32 "
                "{%0, %1, %2, %3, %4, %5, %6, %7, "
                " %8, %9, %10, %11, %12, %13, %14, %15, "
                " %16, %17, %18, %19, %20, %21, %22, %23, "
                " %24, %25, %26, %27, %28, %29, %30, %31}, [%32];"
                : "=r"(r[0]),  "=r"(r[1]),  "=r"(r[2]),  "=r"(r[3]),
                  "=r"(r[4]),  "=r"(r[5]),  "=r"(r[6]),  "=r"(r[7]),
                  "=r"(r[8]),  "=r"(r[9]),  "=r"(r[10]), "=r"(r[11]),
                  "=r"(r[12]), "=r"(r[13]), "=r"(r[14]), "=r"(r[15]),
                  "=r"(r[16]), "=r"(r[17]), "=r"(r[18]), "=r"(r[19]),
                  "=r"(r[20]), "=r"(r[21]), "=r"(r[22]), "=r"(r[23]),
                  "=r"(r[24]), "=r"(r[25]), "=r"(r[26]), "=r"(r[27]),
                  "=r"(r[28]), "=r"(r[29]), "=r"(r[30]), "=r"(r[31])
                : "r"(tmem + ch * 32));
            asm volatile("tcgen05.wait::ld.sync.aligned;" ::: "memory");
            size_t ro = (size_t)row * N + bn + ch * 32;
            if (EPI == 0) {
                #pragma unroll
                for (int j = 0; j < 32; j += 4) {
                    float4 o;
                    o.x = __uint_as_float(r[j]);     o.y = __uint_as_float(r[j + 1]);
                    o.z = __uint_as_float(r[j + 2]); o.w = __uint_as_float(r[j + 3]);
                    *(float4*)(Cf + ro + j) = o;
                }
            } else {
                #pragma unroll
                for (int j = 0; j < 32; j += 2) {
                    float v0 = fmaxf(__uint_as_float(r[j]),     0.f);
                    float v1 = fmaxf(__uint_as_float(r[j + 1]), 0.f);
                    __nv_bfloat16 h0 = __float2bfloat16(v0), h1 = __float2bfloat16(v1);
                    *(__nv_bfloat162*)(Chi + ro + j) = __halves2bfloat162(h0, h1);
                    *(__nv_bfloat162*)(Clo + ro + j) = __halves2bfloat162(
                        __float2bfloat16(v0 - __bfloat162float(h0)),
                        __float2bfloat16(v1 - __bfloat162float(h1)));
                }
            }
        }
    }
    __syncthreads();
    if (wid == 0)
        asm volatile("tcgen05.dealloc.cta_group::1.sync.aligned.b32 %0, %1;"
                     :: "r"(tmem), "r"(256u));
#else
    // Fallback for the non-103a compile pass (never selected at runtime on GB300):
    // straightforward SIMT GEMM over hi+lo operands.
    const int bm = blockIdx.y * BM, bn = blockIdx.x * BN;
    for (int idx = threadIdx.x; idx < BM * BN; idx += 256) {
        int r = idx / BN, c = idx % BN;
        const __nv_bfloat16* arh = Ahi + (size_t)(bm + r) * K;
        const __nv_bfloat16* arl = Alo + (size_t)(bm + r) * K;
        const __nv_bfloat16* brh = Bhi + (size_t)(bn + c) * K;
        const __nv_bfloat16* brl = Blo + (size_t)(bn + c) * K;
        float acc = 0.f;
        for (int kk = 0; kk < K; kk++) {
            float a = __bfloat162float(arh[kk]) + __bfloat162float(arl[kk]);
            float b = __bfloat162float(brh[kk]) + __bfloat162float(brl[kk]);
            acc += a * b;
        }
        size_t ro = (size_t)(bm + r) * N + bn + c;
        if (EPI == 0) {
            Cf[ro] = acc;
        } else {
            float v0 = fmaxf(acc, 0.f);
            __nv_bfloat16 h0 = __float2bfloat16(v0);
            Chi[ro] = h0;
            Clo[ro] = __float2bfloat16(v0 - __bfloat162float(h0));
        }
    }
#endif
}

// ---------------- permutation gathers ----------------
__global__ void __launch_bounds__(256) permute_k(const float* __restrict__ src,
                                                 float* __restrict__ dst, int mode) {
    int i = blockIdx.x * 256 + threadIdx.x;
    if (i >= BS * LL * D) return;
    int b = i / (LL * D);
    int F = i % (LL * D);
    int l0, c0;
    if (mode == 13) {
        int f = F % D; l0 = F / D;
        c0 = (f & 7) * 32 + (f >> 3);
    } else if (mode == 21) {
        int h0 = F / (LL * DH);
        int rem = F % (LL * DH);
        l0 = rem / DH;
        c0 = h0 * 32 + (rem % DH);
    } else {
        int d0 = F / (H * LL);
        int rem = F % (H * LL);
        int h0 = rem / LL;
        l0 = rem % LL;
        c0 = h0 * 32 + d0;
    }
    dst[i] = src[(size_t)b * LL * D + (size_t)l0 * D + c0];
}

// ---------------- KV reduce (split across sequence, atomics) ----------------
#define KVSPLIT 10
#define KVCHUNK (LL/KVSPLIT)
__global__ void __launch_bounds__(256) kv_reduce(const float* __restrict__ k,
                                                 const float* __restrict__ v) {
    int b = blockIdx.x >> 3, h = blockIdx.x & 7;
    int sbeg = blockIdx.y * KVCHUNK;
    const float* kb = k + (size_t)b * LL * D + h * DH;
    const float* vb = v + (size_t)b * LL * D + h * DH;
    __shared__ float ks[8][32], vs[8][32];
    int t = threadIdx.x;
    int r = t >> 5, c = t & 31;
    float acc[4] = {0.f, 0.f, 0.f, 0.f};
    float ksacc = 0.f;
    for (int s0 = sbeg; s0 < sbeg + KVCHUNK; s0 += 8) {
        ks[r][c] = phi(kb[(size_t)(s0 + r) * D + c]);
        vs[r][c] = vb[(size_t)(s0 + r) * D + c];
        __syncthreads();
        #pragma unroll
        for (int row = 0; row < 8; row++) {
            float ve = vs[row][c];
            #pragma unroll
            for (int jj = 0; jj < 4; jj++)
                acc[jj] += ks[row][r + jj * 8] * ve;
        }
        if (t < 32) {
            #pragma unroll
            for (int row = 0; row < 8; row++) ksacc += ks[row][t];
        }
        __syncthreads();
    }
    float* kvout = g_kv + (size_t)(b * H + h) * DH * DH;
    #pragma unroll
    for (int jj = 0; jj < 4; jj++)
        atomicAdd(&kvout[(r + jj * 8) * DH + c], acc[jj]);
    if (t < 32) atomicAdd(&g_ksum[(b * H + h) * DH + t], ksacc);
}

// ---------------- attention apply: writes bf16 hi/lo msg (pitch 256) ----------------
__global__ void __launch_bounds__(256) attn_out(const float* __restrict__ q,
                                                __nv_bfloat16* __restrict__ mhi,
                                                __nv_bfloat16* __restrict__ mlo) {
    int b  = blockIdx.y;
    int l0 = blockIdx.x * TOK;
    __shared__ float sKV[H * DH * DH];
    __shared__ float sKs[H * DH];
    __shared__ float sQ[TOK][D];
    __shared__ float sZ[TOK][H];
    int t = threadIdx.x;
    const float* kvb = g_kv + (size_t)b * H * DH * DH;
    #pragma unroll
    for (int i = t; i < H * DH * DH; i += 256) sKV[i] = kvb[i];
    if (t < H * DH) sKs[t] = g_ksum[b * H * DH + t];
    const float* qb = q + (size_t)b * LL * D + (size_t)l0 * D;
    #pragma unroll
    for (int jj = 0; jj < TOK; jj++) sQ[jj][t] = phi(qb[jj * D + t]);
    __syncthreads();
    if (t < TOK * H) {
        int tok = t / H, h = t % H;
        float z = 0.f;
        #pragma unroll
        for (int d = 0; d < DH; d++) z += sQ[tok][h * DH + d] * sKs[h * DH + d];
        sZ[tok][h] = 1.f / (z + 1e-6f);
    }
    __syncthreads();
    int c = t, h = c >> 5, e = c & 31;
    size_t base = (size_t)b * LL * D + (size_t)l0 * D;
    #pragma unroll
    for (int jj = 0; jj < TOK; jj++) {
        float dot = 0.f;
        #pragma unroll
        for (int d = 0; d < DH; d++)
            dot += sQ[jj][h * DH + d] * sKV[(h * DH + d) * DH + e];
        float m = dot * sZ[jj][h];
        __nv_bfloat16 hi = __float2bfloat16(m);
        mhi[base + jj * D + c] = hi;
        mlo[base + jj * D + c] = __float2bfloat16(m - __bfloat162float(hi));
    }
}

// ---------------- hcat (bf16 hi/lo, pitch 512) = [split(xb) | split(LN(tmp))] ----------------
__global__ void __launch_bounds__(256) build_hcat(const float* __restrict__ tmp,
                                                  const float* __restrict__ xb,
                                                  const float* __restrict__ g,
                                                  const float* __restrict__ bta,
                                                  __nv_bfloat16* __restrict__ hhi,
                                                  __nv_bfloat16* __restrict__ hlo) {
    int warp = threadIdx.x >> 5, lane = threadIdx.x & 31;
    size_t row = (size_t)blockIdx.x * 8 + warp;
    const float* rt = tmp + row * D;
    float v[8]; float s = 0.f;
    #pragma unroll
    for (int i = 0; i < 8; i++) { v[i] = rt[lane + 32 * i]; s += v[i]; }
    s = warp_sum(s);
    float mean = s * (1.f / D);
    float s2 = 0.f;
    #pragma unroll
    for (int i = 0; i < 8; i++) { float d0 = v[i] - mean; s2 += d0 * d0; }
    s2 = warp_sum(s2);
    float rstd = rsqrtf(s2 * (1.f / D) + 1e-5f);
    const float* rx = xb + row * D;
    size_t ro = row * 2 * D;
    #pragma unroll
    for (int i = 0; i < 8; i++) {
        int c = lane + 32 * i;
        float xv = rx[c];
        __nv_bfloat16 xh = __float2bfloat16(xv);
        hhi[ro + c] = xh;
        hlo[ro + c] = __float2bfloat16(xv - __bfloat162float(xh));
        float lv = (v[i] - mean) * rstd * g[c] + bta[c];
        __nv_bfloat16 lh = __float2bfloat16(lv);
        hhi[ro + D + c] = lh;
        hlo[ro + D + c] = __float2bfloat16(lv - __bfloat162float(lh));
    }
}

// ---------------- acc += 0.5 * layernorm(tmp; g2,b2) ----------------
__global__ void __launch_bounds__(256) ln_acc(const float* __restrict__ tmp,
                                              const float* __restrict__ g,
                                              const float* __restrict__ bta,
                                              float* __restrict__ acc) {
    int warp = threadIdx.x >> 5, lane = threadIdx.x & 31;
    size_t row = (size_t)blockIdx.x * 8 + warp;
    const float* rt = tmp + row * D;
    float v[8]; float s = 0.f;
    #pragma unroll
    for (int i = 0; i < 8; i++) { v[i] = rt[lane + 32 * i]; s += v[i]; }
    s = warp_sum(s);
    float mean = s * (1.f / D);
    float s2 = 0.f;
    #pragma unroll
    for (int i = 0; i < 8; i++) { float d0 = v[i] - mean; s2 += d0 * d0; }
    s2 = warp_sum(s2);
    float rstd = rsqrtf(s2 * (1.f / D) + 1e-5f);
    float* ao = acc + row * D;
    #pragma unroll
    for (int i = 0; i < 8; i++) {
        int c = lane + 32 * i;
        ao[c] += 0.5f * ((v[i] - mean) * rstd * g[c] + bta[c]);
    }
}

__global__ void __launch_bounds__(256) copy4(const float4* __restrict__ src,
                                             float4* __restrict__ dst, int n) {
    int i = blockIdx.x * 256 + threadIdx.x;
    if (i < n) dst[i] = src[i];
}

// ---------------- host orchestration ----------------
extern "C" void kernel_launch(void* const* d_in, const int* in_sizes, int n_in,
                              void* d_out, int out_size) {
    (void)in_sizes; (void)n_in; (void)out_size;
    const float* x   = (const float*)d_in[0];
    const float* src = (const float*)d_in[1];
    const float* Wq  = (const float*)d_in[2];
    const float* Wk  = (const float*)d_in[3];
    const float* Wv  = (const float*)d_in[4];
    const float* Wm  = (const float*)d_in[5];
    const float* W1  = (const float*)d_in[6];
    const float* W2  = (const float*)d_in[7];
    const float* g1  = (const float*)d_in[8];
    const float* b1  = (const float*)d_in[9];
    const float* g2  = (const float*)d_in[10];
    const float* b2  = (const float*)d_in[11];
    float* out = (float*)d_out;

    float *q, *k, *v, *qp, *kp, *vp, *tmp, *xmid, *kv, *ksum;
    cudaGetSymbolAddress((void**)&q,    g_q);
    cudaGetSymbolAddress((void**)&k,    g_k);
    cudaGetSymbolAddress((void**)&v,    g_v);
    cudaGetSymbolAddress((void**)&qp,   g_qp);
    cudaGetSymbolAddress((void**)&kp,   g_kp);
    cudaGetSymbolAddress((void**)&vp,   g_vp);
    cudaGetSymbolAddress((void**)&tmp,  g_tmp);
    cudaGetSymbolAddress((void**)&xmid, g_xmid);
    cudaGetSymbolAddress((void**)&kv,   g_kv);
    cudaGetSymbolAddress((void**)&ksum, g_ksum);

    __nv_bfloat16 *xhi, *xlo, *thi, *tlo;
    __nv_bfloat16 *wqh, *wql, *wkh, *wkl, *wvh, *wvl, *wmh, *wml, *w1h, *w1l, *w2h, *w2l;
    cudaGetSymbolAddress((void**)&xhi, g_xhi);
    cudaGetSymbolAddress((void**)&xlo, g_xlo);
    cudaGetSymbolAddress((void**)&thi, g_thi);
    cudaGetSymbolAddress((void**)&tlo, g_tlo);
    cudaGetSymbolAddress((void**)&wqh, g_wqh);  cudaGetSymbolAddress((void**)&wql, g_wql);
    cudaGetSymbolAddress((void**)&wkh, g_wkh);  cudaGetSymbolAddress((void**)&wkl, g_wkl);
    cudaGetSymbolAddress((void**)&wvh, g_wvh);  cudaGetSymbolAddress((void**)&wvl, g_wvl);
    cudaGetSymbolAddress((void**)&wmh, g_wmh);  cudaGetSymbolAddress((void**)&wml, g_wml);
    cudaGetSymbolAddress((void**)&w1h, g_w1h);  cudaGetSymbolAddress((void**)&w1l, g_w1l);
    cudaGetSymbolAddress((void**)&w2h, g_w2h);  cudaGetSymbolAddress((void**)&w2l, g_w2l);

    cudaFuncSetAttribute(tc_gemm<0>, cudaFuncAttributeMaxDynamicSharedMemorySize, SMEM_DYN);
    cudaFuncSetAttribute(tc_gemm<1>, cudaFuncAttributeMaxDynamicSharedMemorySize, SMEM_DYN);

    dim3 thr(256);
    auto gemm = [&](const __nv_bfloat16* ah, const __nv_bfloat16* al,
                    const __nv_bfloat16* bh, const __nv_bfloat16* bl,
                    float* cf, __nv_bfloat16* ch, __nv_bfloat16* cl,
                    int K, int N, int epi) {
        dim3 grid(N / BN, ROWS / BM);
        if (epi) tc_gemm<1><<<grid, thr, SMEM_DYN>>>(ah, al, bh, bl, cf, ch, cl, K, N);
        else     tc_gemm<0><<<grid, thr, SMEM_DYN>>>(ah, al, bh, bl, cf, ch, cl, K, N);
    };

    // weights -> transposed bf16 hi/lo (once)
    wconv<<<(D*D + 255)/256, thr>>>(Wq, wqh, wql, D, D);
    wconv<<<(D*D + 255)/256, thr>>>(Wk, wkh, wkl, D, D);
    wconv<<<(D*D + 255)/256, thr>>>(Wv, wvh, wvl, D, D);
    wconv<<<(D*D + 255)/256, thr>>>(Wm, wmh, wml, D, D);
    wconv<<<(4*D*D + 255)/256, thr>>>(W1, w1h, w1l, 2*D, 2*D);
    wconv<<<(2*D*D + 255)/256, thr>>>(W2, w2h, w2l, 2*D, D);

    // projections
    aconv<<<ROWS*D/4/256, thr>>>((const float4*)x, (__nv_bfloat162*)xhi, (__nv_bfloat162*)xlo, ROWS*D/4);
    gemm(xhi, xlo, wqh, wql, q, nullptr, nullptr, D, D, 0);
    aconv<<<ROWS*D/4/256, thr>>>((const float4*)src, (__nv_bfloat162*)xhi, (__nv_bfloat162*)xlo, ROWS*D/4);
    gemm(xhi, xlo, wkh, wkl, k, nullptr, nullptr, D, D, 0);
    gemm(xhi, xlo, wvh, wvl, v, nullptr, nullptr, D, D, 0);

    copy4<<<ROWS*D/4/256, thr>>>((const float4*)x, (float4*)xmid, ROWS*D/4);

    auto block = [&](const float* xb, int mode, float* accbuf) {
        const float *qq = q, *kk = k, *vv = v;
        if (mode) {
            permute_k<<<ROWS*D/256, thr>>>(q, qp, mode);
            permute_k<<<ROWS*D/256, thr>>>(k, kp, mode);
            permute_k<<<ROWS*D/256, thr>>>(v, vp, mode);
            qq = qp; kk = kp; vv = vp;
        }
        cudaMemsetAsync(kv,   0, (size_t)BS*H*DH*DH*sizeof(float));
        cudaMemsetAsync(ksum, 0, (size_t)BS*H*DH*sizeof(float));
        kv_reduce<<<dim3(BS*H, KVSPLIT), thr>>>(kk, vv);
        attn_out<<<dim3(LL/TOK, BS), thr>>>(qq, xhi, xlo);
        gemm(xhi, xlo, wmh, wml, tmp, nullptr, nullptr, D, D, 0);
        build_hcat<<<ROWS/8, thr>>>(tmp, xb, g1, b1, xhi, xlo);
        gemm(xhi, xlo, w1h, w1l, nullptr, thi, tlo, 2*D, 2*D, 1);
        gemm(thi, tlo, w2h, w2l, tmp, nullptr, nullptr, 2*D, D, 0);
        ln_acc<<<ROWS/8, thr>>>(tmp, g2, b2, accbuf);
    };

    block(x, 0,  xmid);
    block(x, 13, xmid);
    copy4<<<ROWS*D/4/256, thr>>>((const float4*)xmid, (float4*)out, ROWS*D/4);
    block(xmid, 21, out);
    block(xmid, 32, out);
}